// round 10
// baseline (speedup 1.0000x reference)
#include <cuda_runtime.h>
#include <math_constants.h>

#define FULLMASK 0xffffffffu
typedef unsigned long long ull;

static constexpr int Bc = 4;
static constexpr int Nc = 4096;
static constexpr int S1 = 2048;
static constexpr int S2 = 512;
static constexpr int Kc = 64;

// ---------------- scratch (device globals; no allocation allowed) ----------------
__device__ float g_qpos1[Bc * S1 * 3];
__device__ float g_qpos2[Bc * S2 * 3];
__device__ int   g_nidx1[Bc * S1 * Kc];
__device__ int   g_nidx2[Bc * S2 * Kc];
__device__ int   g_cnt1[Bc * S1];
__device__ int   g_cnt2[Bc * S2];
__device__ float g_feat1[Bc * S1 * 64];
__device__ float g_bufA[Bc * S2 * Kc * 64];
__device__ float g_bufB[Bc * S2 * Kc * 64];

// ---------------- packed f32x2 helpers ----------------
__device__ __forceinline__ ull pk2(float lo, float hi) {
    ull r; asm("mov.b64 %0, {%1, %2};" : "=l"(r) : "f"(lo), "f"(hi)); return r;
}
__device__ __forceinline__ void upk2(float& lo, float& hi, ull v) {
    asm("mov.b64 {%0, %1}, %2;" : "=f"(lo), "=f"(hi) : "l"(v));
}
__device__ __forceinline__ ull fma2_(ull a, ull b, ull c) {
    ull d; asm("fma.rn.f32x2 %0, %1, %2, %3;" : "=l"(d) : "l"(a), "l"(b), "l"(c)); return d;
}
__device__ __forceinline__ ull add2_(ull a, ull b) {
    ull d; asm("add.rn.f32x2 %0, %1, %2;" : "=l"(d) : "l"(a), "l"(b)); return d;
}

// ---------------- FPS body: one block per batch, lock-free spin sync ----------------
// d = |p|^2 - 2 p.c + |c|^2 (|p|^2 precomputed), packed f32x2 math.
// Per-warp winner via 2 dependent redux.sync.max.u32 (value, then n-1-idx among
// matching lanes) -> exact lowest-index tie-break of jnp.argmax.
// Cross-warp: lane0 publishes a 64-bit key { [63:32]=value bits, [31:1]=n-1-idx,
// [0]=tag } to skey[step&1][warp]; all lanes spin on slot (lane & NW-1) until
// tag == (step>>1)&1, then 2 more redux. Double-buffer + tag is safe because a
// warp's read phase requires every warp's write for that step, bounding skew to
// one step: buffer[s&1] only ever holds step s or s-2 keys.
template <int NPT, int NTH>
__device__ __forceinline__ void fps_body(const float* __restrict__ pos, int pstride,
                                         int n, int nsamp, float* __restrict__ qpos, int b)
{
    extern __shared__ float4 spts[];
    constexpr int NW = NTH / 32;
    __shared__ ull skey[2][NW];
    const int t = threadIdx.x, lane = t & 31, warp = t >> 5;
    const float* P = pos + (size_t)b * n * pstride;

    ull px2[NPT / 2], py2[NPT / 2], pz2[NPT / 2], nr2[NPT / 2];
    float md[NPT];
    const int i0 = t * NPT;
#pragma unroll
    for (int k2 = 0; k2 < NPT / 2; k2++) {
        const float* pA = P + (size_t)(i0 + 2 * k2) * pstride;
        const float* pB = pA + pstride;
        float ax = pA[0], ay = pA[1], az = pA[2];
        float bx = pB[0], by = pB[1], bz = pB[2];
        float na = __fmaf_rn(az, az, __fmaf_rn(ay, ay, ax * ax));
        float nb = __fmaf_rn(bz, bz, __fmaf_rn(by, by, bx * bx));
        px2[k2] = pk2(ax, bx); py2[k2] = pk2(ay, by);
        pz2[k2] = pk2(az, bz); nr2[k2] = pk2(na, nb);
        spts[i0 + 2 * k2]     = make_float4(ax, ay, az, na);
        spts[i0 + 2 * k2 + 1] = make_float4(bx, by, bz, nb);
        md[2 * k2] = CUDART_INF_F; md[2 * k2 + 1] = CUDART_INF_F;
    }
    // init tags so first expected tag never matches stale data:
    // buf1 first used at step1 (tag 0) -> init tag 1; buf0 first at step2 (tag 1) -> init tag 0
    if (t < NW) { skey[0][t] = 0ull; skey[1][t] = 1ull; }
    __syncthreads();
    float4 c = spts[0];
    if (t == 0) { float* o = qpos + (size_t)b * nsamp * 3; o[0] = c.x; o[1] = c.y; o[2] = c.z; }

    volatile ull* vs0 = skey[0];
    volatile ull* vs1 = skey[1];

    for (int step = 1; step < nsamp; step++) {
        const ull KX = pk2(-2.f * c.x, -2.f * c.x);
        const ull KY = pk2(-2.f * c.y, -2.f * c.y);
        const ull KZ = pk2(-2.f * c.z, -2.f * c.z);
        const ull CC = pk2(c.w, c.w);
        float bm = -CUDART_INF_F; int bi = 0;
#pragma unroll
        for (int k2 = 0; k2 < NPT / 2; k2++) {
            ull e = fma2_(pz2[k2], KZ, nr2[k2]);
            e = fma2_(py2[k2], KY, e);
            e = fma2_(px2[k2], KX, e);
            e = add2_(e, CC);
            float e0, e1; upk2(e0, e1, e);
            float m0 = fminf(md[2 * k2], e0);     md[2 * k2] = m0;
            float m1 = fminf(md[2 * k2 + 1], e1); md[2 * k2 + 1] = m1;
            if (m0 > bm) { bm = m0; bi = i0 + 2 * k2; }
            if (m1 > bm) { bm = m1; bi = i0 + 2 * k2 + 1; }
        }
        bm = fmaxf(bm, 0.0f);   // keep unsigned bit order valid
        unsigned hbits = __float_as_uint(bm);
        unsigned hmax = __reduce_max_sync(FULLMASK, hbits);
        unsigned locand = (hbits == hmax) ? (unsigned)(n - 1 - bi) : 0u;
        unsigned lomax = __reduce_max_sync(FULLMASK, locand);

        const unsigned tag = (unsigned)(step >> 1) & 1u;
        volatile ull* vs = (step & 1) ? vs1 : vs0;
        if (lane == 0)
            vs[warp] = ((ull)hmax << 32) | (ull)(lomax << 1) | (ull)tag;
        ull v;
        do { v = vs[lane & (NW - 1)]; } while ((unsigned)(v & 1ull) != tag);
        unsigned hi = (unsigned)(v >> 32);
        unsigned lo = ((unsigned)v) >> 1;
        unsigned h2m = __reduce_max_sync(FULLMASK, hi);
        unsigned cand = (hi == h2m) ? lo : 0u;
        unsigned l2m = __reduce_max_sync(FULLMASK, cand);
        int wi = n - 1 - (int)l2m;
        c = spts[wi];
        if (t == 0) {
            float* o = qpos + ((size_t)b * nsamp + step) * 3;
            o[0] = c.x; o[1] = c.y; o[2] = c.z;
        }
    }
}

template <int NPT, int NTH>
__global__ void fps_kernel(const float* __restrict__ pos, int pstride, int n, int nsamp,
                           float* __restrict__ qpos)
{
    fps_body<NPT, NTH>(pos, pstride, n, nsamp, qpos, blockIdx.x);
}

// ---------------- Ball query body: warp per query, first K in-range by index ----------------
__device__ __forceinline__ void ball_body(const float* __restrict__ pos, int pstride, int n,
                                          const float* __restrict__ qpos, int S, float r2,
                                          int* __restrict__ nidx, int* __restrict__ cnt_out,
                                          int totalq, int gw)
{
    int lane = threadIdx.x & 31;
    if (gw >= totalq) return;
    int b = gw / S;
    const float* P = pos + (size_t)b * n * pstride;
    const float* q = qpos + (size_t)gw * 3;
    float qx = q[0], qy = q[1], qz = q[2];

    int cnt = 0;
    int* out = nidx + (size_t)gw * Kc;
    for (int base = 0; base < n && cnt < Kc; base += 32) {
        int i = base + lane;
        const float* p = P + (size_t)i * pstride;
        float dx = p[0] - qx, dy = p[1] - qy, dz = p[2] - qz;
        float d = __fmaf_rn(dz, dz, __fmaf_rn(dy, dy, dx * dx));
        bool in = (d <= r2);
        unsigned m = __ballot_sync(FULLMASK, in);
        int pre = __popc(m & ((1u << lane) - 1u));
        int slot = cnt + pre;
        if (in && slot < Kc) out[slot] = i;
        cnt += __popc(m);
    }
    if (cnt > Kc) cnt = Kc;
    for (int j = cnt + lane; j < Kc; j += 32) out[j] = 0;
    if (lane == 0) cnt_out[gw] = cnt;
}

// ---------------- K2: fps2 (blocks 0..3) || ball1 (rest); dyn smem 32KB ----------------
__global__ void __launch_bounds__(256)
k2_fps2_ball1(const float* __restrict__ x, const float* __restrict__ qpos1,
              float* __restrict__ qpos2,
              int* __restrict__ nidx1, int* __restrict__ cnt1)
{
    if (blockIdx.x < Bc) {
        fps_body<8, 256>(qpos1, 3, S1, S2, qpos2, blockIdx.x);
    } else {
        int gw = (blockIdx.x - Bc) * 8 + (threadIdx.x >> 5);
        ball_body(x, 6, Nc, qpos1, S1, 0.25f, nidx1, cnt1, Bc * S1, gw);
    }
}

// ---------------- dense1: 1 item, packed-output FFMA2, relu, float4 stores ----------------
template <int CIN, int COUT>
__device__ __forceinline__ void dense1(const float* h, const float* sW, const float* sB,
                                       float4* __restrict__ o)
{
#pragma unroll 1
    for (int cg = 0; cg < COUT / 4; cg++) {
        ull a01 = pk2(sB[cg * 4 + 0], sB[cg * 4 + 1]);
        ull a23 = pk2(sB[cg * 4 + 2], sB[cg * 4 + 3]);
#pragma unroll
        for (int k = 0; k < CIN; k++) {
            float4 w = *reinterpret_cast<const float4*>(&sW[k * COUT + cg * 4]);
            ull hh = pk2(h[k], h[k]);
            a01 = fma2_(hh, pk2(w.x, w.y), a01);
            a23 = fma2_(hh, pk2(w.z, w.w), a23);
        }
        float x0, x1, x2, x3;
        upk2(x0, x1, a01); upk2(x2, x3, a23);
        o[cg] = make_float4(fmaxf(x0, 0.f), fmaxf(x1, 0.f), fmaxf(x2, 0.f), fmaxf(x3, 0.f));
    }
}

// ---------------- K3: ball2 || fully-fused stage1 (gather->6->32->32->64->maxpool) ----------------
static constexpr int BALL2_BLKS = (Bc * S2) / 4;   // 512 blocks, 4 warps each
__global__ void __launch_bounds__(128)
k3_ball2_fused1(const float* __restrict__ x, const float* __restrict__ qpos1,
                const float* __restrict__ qpos2,
                int* __restrict__ nidx2, int* __restrict__ cnt2,
                const int* __restrict__ nidx1, const int* __restrict__ cnt1,
                const float* __restrict__ W1, const float* __restrict__ B1,
                const float* __restrict__ W2, const float* __restrict__ B2,
                const float* __restrict__ WC, const float* __restrict__ BC,
                float* __restrict__ feat1)
{
    if (blockIdx.x < BALL2_BLKS) {
        int gw = blockIdx.x * 4 + (threadIdx.x >> 5);
        ball_body(qpos1, 3, S1, qpos2, S2, 1.0f, nidx2, cnt2, Bc * S2, gw);
        return;
    }
    __shared__ __align__(16) float sW1[6 * 32];
    __shared__ float sB1[32];
    __shared__ __align__(16) float sW2[32 * 32];
    __shared__ float sB2[32];
    __shared__ __align__(16) float sWC[32 * 64];
    __shared__ float sBC[64];
    __shared__ float sOut[4][64];
    for (int i = threadIdx.x; i < 6 * 32; i += 128) sW1[i] = W1[i];
    if (threadIdx.x < 32) { sB1[threadIdx.x] = B1[threadIdx.x]; sB2[threadIdx.x] = B2[threadIdx.x]; }
    for (int i = threadIdx.x; i < 32 * 32; i += 128) sW2[i] = W2[i];
    for (int i = threadIdx.x; i < 32 * 64; i += 128) sWC[i] = WC[i];
    if (threadIdx.x < 64) sBC[threadIdx.x] = BC[threadIdx.x];
    __syncthreads();

    int lane = threadIdx.x & 31;
    int wl = threadIdx.x >> 5;
    int q = (blockIdx.x - BALL2_BLKS) * 4 + wl;    // 2048 blocks * 4 = 8192 queries
    int b = q >> 11;                                // S1 = 2048
    int c = cnt1[q];
    const float* qq = qpos1 + (size_t)q * 3;
    float qx = qq[0], qy = qq[1], qz = qq[2];

#pragma unroll 1
    for (int r = 0; r < 2; r++) {
        int j = r * 32 + lane;
        int idx = nidx1[(size_t)q * Kc + j];
        const float* rp = x + (size_t)(b * Nc + idx) * 6;
        float h0[6] = { rp[3], rp[4], rp[5], rp[0] - qx, rp[1] - qy, rp[2] - qz };
        float h1[32];
        dense1<6, 32>(h0, sW1, sB1, (float4*)h1);
        float h2[32];
        dense1<32, 32>(h1, sW2, sB2, (float4*)h2);
        bool valid = (j < c);

#pragma unroll 1
        for (int cg = 0; cg < 16; cg++) {
            ull a01 = pk2(sBC[cg * 4 + 0], sBC[cg * 4 + 1]);
            ull a23 = pk2(sBC[cg * 4 + 2], sBC[cg * 4 + 3]);
#pragma unroll
            for (int k = 0; k < 32; k++) {
                float4 w = *reinterpret_cast<const float4*>(&sWC[k * 64 + cg * 4]);
                ull hh = pk2(h2[k], h2[k]);
                a01 = fma2_(hh, pk2(w.x, w.y), a01);
                a23 = fma2_(hh, pk2(w.z, w.w), a23);
            }
            float v0, v1, v2, v3;
            upk2(v0, v1, a01); upk2(v2, v3, a23);
            v0 = valid ? fmaxf(v0, 0.f) : -CUDART_INF_F;
            v1 = valid ? fmaxf(v1, 0.f) : -CUDART_INF_F;
            v2 = valid ? fmaxf(v2, 0.f) : -CUDART_INF_F;
            v3 = valid ? fmaxf(v3, 0.f) : -CUDART_INF_F;
#pragma unroll
            for (int off = 16; off; off >>= 1) {
                v0 = fmaxf(v0, __shfl_down_sync(FULLMASK, v0, off));
                v1 = fmaxf(v1, __shfl_down_sync(FULLMASK, v1, off));
                v2 = fmaxf(v2, __shfl_down_sync(FULLMASK, v2, off));
                v3 = fmaxf(v3, __shfl_down_sync(FULLMASK, v3, off));
            }
            if (lane == 0) {
                if (r == 0) {
                    sOut[wl][cg * 4 + 0] = v0; sOut[wl][cg * 4 + 1] = v1;
                    sOut[wl][cg * 4 + 2] = v2; sOut[wl][cg * 4 + 3] = v3;
                } else {
                    sOut[wl][cg * 4 + 0] = fmaxf(sOut[wl][cg * 4 + 0], v0);
                    sOut[wl][cg * 4 + 1] = fmaxf(sOut[wl][cg * 4 + 1], v1);
                    sOut[wl][cg * 4 + 2] = fmaxf(sOut[wl][cg * 4 + 2], v2);
                    sOut[wl][cg * 4 + 3] = fmaxf(sOut[wl][cg * 4 + 3], v3);
                }
            }
        }
    }
    __syncwarp();
    for (int c0 = lane; c0 < 64; c0 += 32)
        feat1[(size_t)q * 64 + c0] = sOut[wl][c0];
}

// ---------------- Stage2 layer A: gather [feat64, dpos3] -> 67->64, 1 item/thread ----------------
__global__ void __launch_bounds__(128)
layerA2_kernel(const float* __restrict__ feat1, const float* __restrict__ pos1,
               const float* __restrict__ qpos2, const int* __restrict__ nidx,
               const float* __restrict__ W, const float* __restrict__ Bb,
               float* __restrict__ out)
{
    __shared__ __align__(16) float sW[67 * 64];
    __shared__ float sB[64];
    for (int i = threadIdx.x; i < 67 * 64; i += 128) sW[i] = W[i];
    if (threadIdx.x < 64) sB[threadIdx.x] = Bb[threadIdx.x];
    __syncthreads();

    int t = blockIdx.x * 128 + threadIdx.x;
    int q = t >> 6;
    int b = q >> 9;
    int idx = nidx[t];
    const float* f = feat1 + (size_t)(b * S1 + idx) * 64;
    const float* pp = pos1 + (size_t)(b * S1 + idx) * 3;
    const float* qq = qpos2 + (size_t)q * 3;

    float h0[67];
#pragma unroll
    for (int k = 0; k < 64; k += 4) {
        float4 v = *reinterpret_cast<const float4*>(f + k);
        h0[k] = v.x; h0[k + 1] = v.y; h0[k + 2] = v.z; h0[k + 3] = v.w;
    }
    h0[64] = pp[0] - qq[0]; h0[65] = pp[1] - qq[1]; h0[66] = pp[2] - qq[2];
    dense1<67, 64>(h0, sW, sB, (float4*)(out + (size_t)t * 64));
}

// ---------------- Stage2 layer B: 64->64, 1 item/thread ----------------
__global__ void __launch_bounds__(128)
layerB2_kernel(const float* __restrict__ in, const float* __restrict__ W,
               const float* __restrict__ Bb, float* __restrict__ out)
{
    __shared__ __align__(16) float sW[64 * 64];
    __shared__ float sB[64];
    for (int i = threadIdx.x; i < 64 * 64; i += 128) sW[i] = W[i];
    if (threadIdx.x < 64) sB[threadIdx.x] = Bb[threadIdx.x];
    __syncthreads();

    int t = blockIdx.x * 128 + threadIdx.x;
    float h[64];
    const float* f = in + (size_t)t * 64;
#pragma unroll
    for (int k = 0; k < 64; k += 4) {
        float4 v = *reinterpret_cast<const float4*>(f + k);
        h[k] = v.x; h[k + 1] = v.y; h[k + 2] = v.z; h[k + 3] = v.w;
    }
    dense1<64, 64>(h, sW, sB, (float4*)(out + (size_t)t * 64));
}

// ---------------- Stage2 layer C + masked max-pool (warp/query, 2 nbrs/lane) ----------------
template <int C2, int COUT, int NTH, bool TAIL>
__global__ void __launch_bounds__(NTH)
layerC_kernel(const float* __restrict__ in, const int* __restrict__ cnt,
              const float* __restrict__ W, const float* __restrict__ bias,
              float* __restrict__ out, int totalq,
              const float* __restrict__ qpos2, int mode)
{
    constexpr int NW = NTH / 32;
    if (TAIL && (int)blockIdx.x >= totalq / NW) {
        if (mode) {
            int i = ((int)blockIdx.x - totalq / NW) * NTH + threadIdx.x;
            const int featN = Bc * S2 * 128;
            const int posN = Bc * S2 * 3;
            if (i < posN) out[featN + i] = qpos2[i];
            if (mode >= 2 && i < Bc * S2) out[featN + posN + i] = (float)(i / S2);
        }
        return;
    }
    __shared__ __align__(16) float sW[C2 * COUT];
    __shared__ float sB[COUT];
    for (int i = threadIdx.x; i < C2 * COUT; i += NTH) sW[i] = W[i];
    for (int i = threadIdx.x; i < COUT; i += NTH) sB[i] = bias[i];
    __syncthreads();

    int lane = threadIdx.x & 31;
    int wl = threadIdx.x >> 5;
    int q = blockIdx.x * NW + wl;
    if (q >= totalq) return;
    int c = cnt[q];
    bool va = lane < c, vb = lane + 32 < c;

    float ha[C2], hb[C2];
    const float* fa = in + ((size_t)q * Kc + lane) * C2;
    const float* fb = fa + 32 * C2;
#pragma unroll
    for (int k = 0; k < C2; k += 4) {
        float4 u = *reinterpret_cast<const float4*>(fa + k);
        float4 v = *reinterpret_cast<const float4*>(fb + k);
        ha[k] = u.x; ha[k + 1] = u.y; ha[k + 2] = u.z; ha[k + 3] = u.w;
        hb[k] = v.x; hb[k + 1] = v.y; hb[k + 2] = v.z; hb[k + 3] = v.w;
    }

#pragma unroll 1
    for (int cg = 0; cg < COUT / 4; cg++) {
        ull a01 = pk2(sB[cg * 4 + 0], sB[cg * 4 + 1]);
        ull a23 = pk2(sB[cg * 4 + 2], sB[cg * 4 + 3]);
        ull b01 = a01, b23 = a23;
#pragma unroll
        for (int k = 0; k < C2; k++) {
            float4 w = *reinterpret_cast<const float4*>(&sW[k * COUT + cg * 4]);
            ull w01 = pk2(w.x, w.y), w23 = pk2(w.z, w.w);
            ull hA = pk2(ha[k], ha[k]);
            ull hB = pk2(hb[k], hb[k]);
            a01 = fma2_(hA, w01, a01); a23 = fma2_(hA, w23, a23);
            b01 = fma2_(hB, w01, b01); b23 = fma2_(hB, w23, b23);
        }
        float x0, x1, x2, x3, y0, y1, y2, y3;
        upk2(x0, x1, a01); upk2(x2, x3, a23);
        upk2(y0, y1, b01); upk2(y2, y3, b23);
        x0 = va ? fmaxf(x0, 0.f) : -CUDART_INF_F;
        x1 = va ? fmaxf(x1, 0.f) : -CUDART_INF_F;
        x2 = va ? fmaxf(x2, 0.f) : -CUDART_INF_F;
        x3 = va ? fmaxf(x3, 0.f) : -CUDART_INF_F;
        y0 = vb ? fmaxf(y0, 0.f) : -CUDART_INF_F;
        y1 = vb ? fmaxf(y1, 0.f) : -CUDART_INF_F;
        y2 = vb ? fmaxf(y2, 0.f) : -CUDART_INF_F;
        y3 = vb ? fmaxf(y3, 0.f) : -CUDART_INF_F;
        float v0 = fmaxf(x0, y0), v1 = fmaxf(x1, y1);
        float v2 = fmaxf(x2, y2), v3 = fmaxf(x3, y3);
#pragma unroll
        for (int off = 16; off; off >>= 1) {
            v0 = fmaxf(v0, __shfl_down_sync(FULLMASK, v0, off));
            v1 = fmaxf(v1, __shfl_down_sync(FULLMASK, v1, off));
            v2 = fmaxf(v2, __shfl_down_sync(FULLMASK, v2, off));
            v3 = fmaxf(v3, __shfl_down_sync(FULLMASK, v3, off));
        }
        if (lane == 0)
            *reinterpret_cast<float4*>(out + (size_t)q * COUT + cg * 4) =
                make_float4(v0, v1, v2, v3);
    }
}

extern "C" void kernel_launch(void* const* d_in, const int* in_sizes, int n_in,
                              void* d_out, int out_size)
{
    const float* x   = (const float*)d_in[0];
    const float* w1a = (const float*)d_in[1];  const float* b1a = (const float*)d_in[2];
    const float* w1b = (const float*)d_in[3];  const float* b1b = (const float*)d_in[4];
    const float* w1c = (const float*)d_in[5];  const float* b1c = (const float*)d_in[6];
    const float* w2a = (const float*)d_in[7];  const float* b2a = (const float*)d_in[8];
    const float* w2b = (const float*)d_in[9];  const float* b2b = (const float*)d_in[10];
    const float* w2c = (const float*)d_in[11]; const float* b2c = (const float*)d_in[12];
    float* out = (float*)d_out;

    void *pq1, *pq2, *pn1, *pn2, *pc1, *pc2, *pf1, *pa, *pb;
    cudaGetSymbolAddress(&pq1, g_qpos1);
    cudaGetSymbolAddress(&pq2, g_qpos2);
    cudaGetSymbolAddress(&pn1, g_nidx1);
    cudaGetSymbolAddress(&pn2, g_nidx2);
    cudaGetSymbolAddress(&pc1, g_cnt1);
    cudaGetSymbolAddress(&pc2, g_cnt2);
    cudaGetSymbolAddress(&pf1, g_feat1);
    cudaGetSymbolAddress(&pa, g_bufA);
    cudaGetSymbolAddress(&pb, g_bufB);
    float* qpos1 = (float*)pq1;  float* qpos2 = (float*)pq2;
    int* nidx1 = (int*)pn1;      int* nidx2 = (int*)pn2;
    int* cnt1 = (int*)pc1;       int* cnt2 = (int*)pc2;
    float* feat1 = (float*)pf1;  float* bufA = (float*)pa;  float* bufB = (float*)pb;

    // fps1 needs 64KB dynamic smem (4096 float4)
    cudaFuncSetAttribute((const void*)fps_kernel<16, 256>,
                         cudaFuncAttributeMaxDynamicSharedMemorySize, Nc * 16);

    const int featN = Bc * S2 * 128;
    const int posN = Bc * S2 * 3;
    int mode = 0;
    if (out_size >= featN + posN) mode = 1;
    if (out_size >= featN + posN + Bc * S2) mode = 2;

    // K1: fps stage1 (N=4096 -> S1=2048)
    fps_kernel<16, 256><<<Bc, 256, Nc * 16>>>(x, 6, Nc, S1, qpos1);

    // K2: fps stage2 overlapped with ball query stage1
    {
        int ballBlks = (Bc * S1) / 8;
        k2_fps2_ball1<<<Bc + ballBlks, 256, S1 * 16>>>(x, qpos1, qpos2, nidx1, cnt1);
    }

    // K3: ball query stage2 overlapped with fully-fused stage1 MLP+maxpool
    {
        int fusedBlks = (Bc * S1) / 4;          // 2048
        k3_ball2_fused1<<<BALL2_BLKS + fusedBlks, 128>>>(
            x, qpos1, qpos2, nidx2, cnt2, nidx1, cnt1,
            w1a, b1a, w1b, b1b, w1c, b1c, feat1);
    }

    // K4/K5: stage2 MLP A, B
    layerA2_kernel<<<(Bc * S2 * Kc) / 128, 128>>>(feat1, qpos1, qpos2, nidx2, w2a, b2a, bufA);
    layerB2_kernel<<<(Bc * S2 * Kc) / 128, 128>>>(bufA, w2b, b2b, bufB);

    // K6: stage2 layer C + maxpool, with tail blocks for optional pos/batch outputs
    {
        int nq = (Bc * S2) / 4;
        int tailBlks = (posN + 127) / 128 + 1;
        layerC_kernel<64, 128, 128, true><<<nq + tailBlks, 128>>>(
            bufB, cnt2, w2c, b2c, out, Bc * S2, qpos2, mode);
    }
}

// round 11
// speedup vs baseline: 2.1338x; 2.1338x over previous
#include <cuda_runtime.h>
#include <math_constants.h>

#define FULLMASK 0xffffffffu
typedef unsigned long long ull;

static constexpr int Bc = 4;
static constexpr int Nc = 4096;
static constexpr int S1 = 2048;
static constexpr int S2 = 512;
static constexpr int Kc = 64;

// ---------------- scratch (device globals; no allocation allowed) ----------------
__device__ float g_qpos1[Bc * S1 * 3];
__device__ float g_qpos2[Bc * S2 * 3];
__device__ int   g_nidx1[Bc * S1 * Kc];
__device__ int   g_nidx2[Bc * S2 * Kc];
__device__ int   g_cnt1[Bc * S1];
__device__ int   g_cnt2[Bc * S2];
__device__ float g_feat1[Bc * S1 * 64];
__device__ float g_bufA[Bc * S2 * Kc * 64];
__device__ float g_bufB[Bc * S2 * Kc * 64];

// ---------------- packed f32x2 helpers ----------------
__device__ __forceinline__ ull pk2(float lo, float hi) {
    ull r; asm("mov.b64 %0, {%1, %2};" : "=l"(r) : "f"(lo), "f"(hi)); return r;
}
__device__ __forceinline__ void upk2(float& lo, float& hi, ull v) {
    asm("mov.b64 {%0, %1}, %2;" : "=f"(lo), "=f"(hi) : "l"(v));
}
__device__ __forceinline__ ull fma2_(ull a, ull b, ull c) {
    ull d; asm("fma.rn.f32x2 %0, %1, %2, %3;" : "=l"(d) : "l"(a), "l"(b), "l"(c)); return d;
}
__device__ __forceinline__ ull add2_(ull a, ull b) {
    ull d; asm("add.rn.f32x2 %0, %1, %2;" : "=l"(d) : "l"(a), "l"(b)); return d;
}

// ---------------- FPS body (PROVEN R8 version): __syncthreads + REDUX ----------------
// d = |p|^2 - 2 p.c + |c|^2 (|p|^2 precomputed), packed f32x2 math.
// Warp winner via 2 dependent redux.sync.max.u32 (value, then n-1-idx among
// matching lanes) -> exact lowest-index tie-break of jnp.argmax.
// skey double-buffered by step parity; one __syncthreads per step.
// NOTE: a volatile-smem spin-sync variant was tried and regressed +1.27ms —
// spinning warps steal issue slots and each poll is a ~29cyc LDS. Do not retry.
template <int NPT, int NTH>
__device__ __forceinline__ void fps_body(const float* __restrict__ pos, int pstride,
                                         int n, int nsamp, float* __restrict__ qpos, int b)
{
    extern __shared__ float4 spts[];
    constexpr int NW = NTH / 32;
    __shared__ ull skey[2][NW];
    const int t = threadIdx.x, lane = t & 31, warp = t >> 5;
    const float* P = pos + (size_t)b * n * pstride;

    ull px2[NPT / 2], py2[NPT / 2], pz2[NPT / 2], nr2[NPT / 2];
    float md[NPT];
    const int i0 = t * NPT;
#pragma unroll
    for (int k2 = 0; k2 < NPT / 2; k2++) {
        const float* pA = P + (size_t)(i0 + 2 * k2) * pstride;
        const float* pB = pA + pstride;
        float ax = pA[0], ay = pA[1], az = pA[2];
        float bx = pB[0], by = pB[1], bz = pB[2];
        float na = __fmaf_rn(az, az, __fmaf_rn(ay, ay, ax * ax));
        float nb = __fmaf_rn(bz, bz, __fmaf_rn(by, by, bx * bx));
        px2[k2] = pk2(ax, bx); py2[k2] = pk2(ay, by);
        pz2[k2] = pk2(az, bz); nr2[k2] = pk2(na, nb);
        spts[i0 + 2 * k2]     = make_float4(ax, ay, az, na);
        spts[i0 + 2 * k2 + 1] = make_float4(bx, by, bz, nb);
        md[2 * k2] = CUDART_INF_F; md[2 * k2 + 1] = CUDART_INF_F;
    }
    __syncthreads();
    float4 c = spts[0];
    if (t == 0) { float* o = qpos + (size_t)b * nsamp * 3; o[0] = c.x; o[1] = c.y; o[2] = c.z; }

    for (int step = 1; step < nsamp; step++) {
        const ull KX = pk2(-2.f * c.x, -2.f * c.x);
        const ull KY = pk2(-2.f * c.y, -2.f * c.y);
        const ull KZ = pk2(-2.f * c.z, -2.f * c.z);
        const ull CC = pk2(c.w, c.w);
        float bm = -CUDART_INF_F; int bi = 0;
#pragma unroll
        for (int k2 = 0; k2 < NPT / 2; k2++) {
            ull e = fma2_(pz2[k2], KZ, nr2[k2]);
            e = fma2_(py2[k2], KY, e);
            e = fma2_(px2[k2], KX, e);
            e = add2_(e, CC);
            float e0, e1; upk2(e0, e1, e);
            float m0 = fminf(md[2 * k2], e0);     md[2 * k2] = m0;
            float m1 = fminf(md[2 * k2 + 1], e1); md[2 * k2 + 1] = m1;
            if (m0 > bm) { bm = m0; bi = i0 + 2 * k2; }
            if (m1 > bm) { bm = m1; bi = i0 + 2 * k2 + 1; }
        }
        bm = fmaxf(bm, 0.0f);   // keep unsigned bit order valid
        unsigned hbits = __float_as_uint(bm);
        unsigned hmax = __reduce_max_sync(FULLMASK, hbits);
        unsigned locand = (hbits == hmax) ? (unsigned)(n - 1 - bi) : 0u;
        unsigned lomax = __reduce_max_sync(FULLMASK, locand);
        if (lane == 0) skey[step & 1][warp] = ((ull)hmax << 32) | lomax;
        __syncthreads();
        ull best = skey[step & 1][0];
#pragma unroll
        for (int w = 1; w < NW; w++) {
            ull o = skey[step & 1][w];
            if (o > best) best = o;
        }
        int wi = n - 1 - (int)(unsigned)(best & 0xffffffffull);
        c = spts[wi];
        if (t == 0) {
            float* o = qpos + ((size_t)b * nsamp + step) * 3;
            o[0] = c.x; o[1] = c.y; o[2] = c.z;
        }
    }
}

template <int NPT, int NTH>
__global__ void fps_kernel(const float* __restrict__ pos, int pstride, int n, int nsamp,
                           float* __restrict__ qpos)
{
    fps_body<NPT, NTH>(pos, pstride, n, nsamp, qpos, blockIdx.x);
}

// ---------------- Ball query body: warp per query, first K in-range by index ----------------
__device__ __forceinline__ void ball_body(const float* __restrict__ pos, int pstride, int n,
                                          const float* __restrict__ qpos, int S, float r2,
                                          int* __restrict__ nidx, int* __restrict__ cnt_out,
                                          int totalq, int gw)
{
    int lane = threadIdx.x & 31;
    if (gw >= totalq) return;
    int b = gw / S;
    const float* P = pos + (size_t)b * n * pstride;
    const float* q = qpos + (size_t)gw * 3;
    float qx = q[0], qy = q[1], qz = q[2];

    int cnt = 0;
    int* out = nidx + (size_t)gw * Kc;
    for (int base = 0; base < n && cnt < Kc; base += 32) {
        int i = base + lane;
        const float* p = P + (size_t)i * pstride;
        float dx = p[0] - qx, dy = p[1] - qy, dz = p[2] - qz;
        float d = __fmaf_rn(dz, dz, __fmaf_rn(dy, dy, dx * dx));
        bool in = (d <= r2);
        unsigned m = __ballot_sync(FULLMASK, in);
        int pre = __popc(m & ((1u << lane) - 1u));
        int slot = cnt + pre;
        if (in && slot < Kc) out[slot] = i;
        cnt += __popc(m);
    }
    if (cnt > Kc) cnt = Kc;
    for (int j = cnt + lane; j < Kc; j += 32) out[j] = 0;
    if (lane == 0) cnt_out[gw] = cnt;
}

// ---------------- K2: fps2 (blocks 0..3) || ball1 (rest); dyn smem 32KB ----------------
__global__ void __launch_bounds__(256)
k2_fps2_ball1(const float* __restrict__ x, const float* __restrict__ qpos1,
              float* __restrict__ qpos2,
              int* __restrict__ nidx1, int* __restrict__ cnt1)
{
    if (blockIdx.x < Bc) {
        fps_body<8, 256>(qpos1, 3, S1, S2, qpos2, blockIdx.x);
    } else {
        int gw = (blockIdx.x - Bc) * 8 + (threadIdx.x >> 5);
        ball_body(x, 6, Nc, qpos1, S1, 0.25f, nidx1, cnt1, Bc * S1, gw);
    }
}

// ---------------- dense1: 1 item, 4 independent FFMA2 chains (8 outputs/pass) ----------------
// occ/issue profiling showed 2-chain version is dependency-latency bound; 4 chains
// double ILP at identical LDS.128 count.
template <int CIN, int COUT>
__device__ __forceinline__ void dense1(const float* h, const float* sW, const float* sB,
                                       float4* __restrict__ o)
{
    static_assert(COUT % 8 == 0, "COUT must be multiple of 8");
#pragma unroll 1
    for (int cg = 0; cg < COUT / 8; cg++) {
        ull a01 = pk2(sB[cg * 8 + 0], sB[cg * 8 + 1]);
        ull a23 = pk2(sB[cg * 8 + 2], sB[cg * 8 + 3]);
        ull a45 = pk2(sB[cg * 8 + 4], sB[cg * 8 + 5]);
        ull a67 = pk2(sB[cg * 8 + 6], sB[cg * 8 + 7]);
#pragma unroll
        for (int k = 0; k < CIN; k++) {
            float4 w0 = *reinterpret_cast<const float4*>(&sW[k * COUT + cg * 8]);
            float4 w1 = *reinterpret_cast<const float4*>(&sW[k * COUT + cg * 8 + 4]);
            ull hh = pk2(h[k], h[k]);
            a01 = fma2_(hh, pk2(w0.x, w0.y), a01);
            a23 = fma2_(hh, pk2(w0.z, w0.w), a23);
            a45 = fma2_(hh, pk2(w1.x, w1.y), a45);
            a67 = fma2_(hh, pk2(w1.z, w1.w), a67);
        }
        float x0, x1, x2, x3, x4, x5, x6, x7;
        upk2(x0, x1, a01); upk2(x2, x3, a23);
        upk2(x4, x5, a45); upk2(x6, x7, a67);
        o[cg * 2]     = make_float4(fmaxf(x0, 0.f), fmaxf(x1, 0.f), fmaxf(x2, 0.f), fmaxf(x3, 0.f));
        o[cg * 2 + 1] = make_float4(fmaxf(x4, 0.f), fmaxf(x5, 0.f), fmaxf(x6, 0.f), fmaxf(x7, 0.f));
    }
}

// ---------------- K3: ball2 || fully-fused stage1 (gather->6->32->32->64->maxpool) ----------------
static constexpr int BALL2_BLKS = (Bc * S2) / 4;   // 512 blocks, 4 warps each
__global__ void __launch_bounds__(128)
k3_ball2_fused1(const float* __restrict__ x, const float* __restrict__ qpos1,
                const float* __restrict__ qpos2,
                int* __restrict__ nidx2, int* __restrict__ cnt2,
                const int* __restrict__ nidx1, const int* __restrict__ cnt1,
                const float* __restrict__ W1, const float* __restrict__ B1,
                const float* __restrict__ W2, const float* __restrict__ B2,
                const float* __restrict__ WC, const float* __restrict__ BC,
                float* __restrict__ feat1)
{
    if (blockIdx.x < BALL2_BLKS) {
        int gw = blockIdx.x * 4 + (threadIdx.x >> 5);
        ball_body(qpos1, 3, S1, qpos2, S2, 1.0f, nidx2, cnt2, Bc * S2, gw);
        return;
    }
    __shared__ __align__(16) float sW1[6 * 32];
    __shared__ float sB1[32];
    __shared__ __align__(16) float sW2[32 * 32];
    __shared__ float sB2[32];
    __shared__ __align__(16) float sWC[32 * 64];
    __shared__ float sBC[64];
    __shared__ float sOut[4][64];
    for (int i = threadIdx.x; i < 6 * 32; i += 128) sW1[i] = W1[i];
    if (threadIdx.x < 32) { sB1[threadIdx.x] = B1[threadIdx.x]; sB2[threadIdx.x] = B2[threadIdx.x]; }
    for (int i = threadIdx.x; i < 32 * 32; i += 128) sW2[i] = W2[i];
    for (int i = threadIdx.x; i < 32 * 64; i += 128) sWC[i] = WC[i];
    if (threadIdx.x < 64) sBC[threadIdx.x] = BC[threadIdx.x];
    __syncthreads();

    int lane = threadIdx.x & 31;
    int wl = threadIdx.x >> 5;
    int q = (blockIdx.x - BALL2_BLKS) * 4 + wl;    // 2048 blocks * 4 = 8192 queries
    int b = q >> 11;                                // S1 = 2048
    int c = cnt1[q];
    const float* qq = qpos1 + (size_t)q * 3;
    float qx = qq[0], qy = qq[1], qz = qq[2];

#pragma unroll 1
    for (int r = 0; r < 2; r++) {
        int j = r * 32 + lane;
        int idx = nidx1[(size_t)q * Kc + j];
        const float* rp = x + (size_t)(b * Nc + idx) * 6;
        float h0[6] = { rp[3], rp[4], rp[5], rp[0] - qx, rp[1] - qy, rp[2] - qz };
        float h1[32];
        dense1<6, 32>(h0, sW1, sB1, (float4*)h1);
        float h2[32];
        dense1<32, 32>(h1, sW2, sB2, (float4*)h2);
        bool valid = (j < c);

#pragma unroll 1
        for (int cg = 0; cg < 8; cg++) {            // 8 outputs per pass, 4 chains
            ull a01 = pk2(sBC[cg * 8 + 0], sBC[cg * 8 + 1]);
            ull a23 = pk2(sBC[cg * 8 + 2], sBC[cg * 8 + 3]);
            ull a45 = pk2(sBC[cg * 8 + 4], sBC[cg * 8 + 5]);
            ull a67 = pk2(sBC[cg * 8 + 6], sBC[cg * 8 + 7]);
#pragma unroll
            for (int k = 0; k < 32; k++) {
                float4 w0 = *reinterpret_cast<const float4*>(&sWC[k * 64 + cg * 8]);
                float4 w1 = *reinterpret_cast<const float4*>(&sWC[k * 64 + cg * 8 + 4]);
                ull hh = pk2(h2[k], h2[k]);
                a01 = fma2_(hh, pk2(w0.x, w0.y), a01);
                a23 = fma2_(hh, pk2(w0.z, w0.w), a23);
                a45 = fma2_(hh, pk2(w1.x, w1.y), a45);
                a67 = fma2_(hh, pk2(w1.z, w1.w), a67);
            }
            float v[8];
            upk2(v[0], v[1], a01); upk2(v[2], v[3], a23);
            upk2(v[4], v[5], a45); upk2(v[6], v[7], a67);
#pragma unroll
            for (int u = 0; u < 8; u++) {
                float vv = valid ? fmaxf(v[u], 0.f) : -CUDART_INF_F;
#pragma unroll
                for (int off = 16; off; off >>= 1)
                    vv = fmaxf(vv, __shfl_down_sync(FULLMASK, vv, off));
                v[u] = vv;
            }
            if (lane == 0) {
                if (r == 0) {
#pragma unroll
                    for (int u = 0; u < 8; u++) sOut[wl][cg * 8 + u] = v[u];
                } else {
#pragma unroll
                    for (int u = 0; u < 8; u++)
                        sOut[wl][cg * 8 + u] = fmaxf(sOut[wl][cg * 8 + u], v[u]);
                }
            }
        }
    }
    __syncwarp();
    for (int c0 = lane; c0 < 64; c0 += 32)
        feat1[(size_t)q * 64 + c0] = sOut[wl][c0];
}

// ---------------- Stage2 layer A: gather [feat64, dpos3] -> 67->64, 1 item/thread ----------------
__global__ void __launch_bounds__(128)
layerA2_kernel(const float* __restrict__ feat1, const float* __restrict__ pos1,
               const float* __restrict__ qpos2, const int* __restrict__ nidx,
               const float* __restrict__ W, const float* __restrict__ Bb,
               float* __restrict__ out)
{
    __shared__ __align__(16) float sW[67 * 64];
    __shared__ float sB[64];
    for (int i = threadIdx.x; i < 67 * 64; i += 128) sW[i] = W[i];
    if (threadIdx.x < 64) sB[threadIdx.x] = Bb[threadIdx.x];
    __syncthreads();

    int t = blockIdx.x * 128 + threadIdx.x;
    int q = t >> 6;
    int b = q >> 9;
    int idx = nidx[t];
    const float* f = feat1 + (size_t)(b * S1 + idx) * 64;
    const float* pp = pos1 + (size_t)(b * S1 + idx) * 3;
    const float* qq = qpos2 + (size_t)q * 3;

    float h0[67];
#pragma unroll
    for (int k = 0; k < 64; k += 4) {
        float4 v = *reinterpret_cast<const float4*>(f + k);
        h0[k] = v.x; h0[k + 1] = v.y; h0[k + 2] = v.z; h0[k + 3] = v.w;
    }
    h0[64] = pp[0] - qq[0]; h0[65] = pp[1] - qq[1]; h0[66] = pp[2] - qq[2];
    dense1<67, 64>(h0, sW, sB, (float4*)(out + (size_t)t * 64));
}

// ---------------- Stage2 layer B: 64->64, 1 item/thread ----------------
__global__ void __launch_bounds__(128)
layerB2_kernel(const float* __restrict__ in, const float* __restrict__ W,
               const float* __restrict__ Bb, float* __restrict__ out)
{
    __shared__ __align__(16) float sW[64 * 64];
    __shared__ float sB[64];
    for (int i = threadIdx.x; i < 64 * 64; i += 128) sW[i] = W[i];
    if (threadIdx.x < 64) sB[threadIdx.x] = Bb[threadIdx.x];
    __syncthreads();

    int t = blockIdx.x * 128 + threadIdx.x;
    float h[64];
    const float* f = in + (size_t)t * 64;
#pragma unroll
    for (int k = 0; k < 64; k += 4) {
        float4 v = *reinterpret_cast<const float4*>(f + k);
        h[k] = v.x; h[k + 1] = v.y; h[k + 2] = v.z; h[k + 3] = v.w;
    }
    dense1<64, 64>(h, sW, sB, (float4*)(out + (size_t)t * 64));
}

// ---------------- Stage2 layer C + masked max-pool (warp/query, 2 nbrs/lane) ----------------
template <int C2, int COUT, int NTH, bool TAIL>
__global__ void __launch_bounds__(NTH)
layerC_kernel(const float* __restrict__ in, const int* __restrict__ cnt,
              const float* __restrict__ W, const float* __restrict__ bias,
              float* __restrict__ out, int totalq,
              const float* __restrict__ qpos2, int mode)
{
    constexpr int NW = NTH / 32;
    if (TAIL && (int)blockIdx.x >= totalq / NW) {
        if (mode) {
            int i = ((int)blockIdx.x - totalq / NW) * NTH + threadIdx.x;
            const int featN = Bc * S2 * 128;
            const int posN = Bc * S2 * 3;
            if (i < posN) out[featN + i] = qpos2[i];
            if (mode >= 2 && i < Bc * S2) out[featN + posN + i] = (float)(i / S2);
        }
        return;
    }
    __shared__ __align__(16) float sW[C2 * COUT];
    __shared__ float sB[COUT];
    for (int i = threadIdx.x; i < C2 * COUT; i += NTH) sW[i] = W[i];
    for (int i = threadIdx.x; i < COUT; i += NTH) sB[i] = bias[i];
    __syncthreads();

    int lane = threadIdx.x & 31;
    int wl = threadIdx.x >> 5;
    int q = blockIdx.x * NW + wl;
    if (q >= totalq) return;
    int c = cnt[q];
    bool va = lane < c, vb = lane + 32 < c;

    float ha[C2], hb[C2];
    const float* fa = in + ((size_t)q * Kc + lane) * C2;
    const float* fb = fa + 32 * C2;
#pragma unroll
    for (int k = 0; k < C2; k += 4) {
        float4 u = *reinterpret_cast<const float4*>(fa + k);
        float4 v = *reinterpret_cast<const float4*>(fb + k);
        ha[k] = u.x; ha[k + 1] = u.y; ha[k + 2] = u.z; ha[k + 3] = u.w;
        hb[k] = v.x; hb[k + 1] = v.y; hb[k + 2] = v.z; hb[k + 3] = v.w;
    }

#pragma unroll 1
    for (int cg = 0; cg < COUT / 4; cg++) {
        ull a01 = pk2(sB[cg * 4 + 0], sB[cg * 4 + 1]);
        ull a23 = pk2(sB[cg * 4 + 2], sB[cg * 4 + 3]);
        ull b01 = a01, b23 = a23;
#pragma unroll
        for (int k = 0; k < C2; k++) {
            float4 w = *reinterpret_cast<const float4*>(&sW[k * COUT + cg * 4]);
            ull w01 = pk2(w.x, w.y), w23 = pk2(w.z, w.w);
            ull hA = pk2(ha[k], ha[k]);
            ull hB = pk2(hb[k], hb[k]);
            a01 = fma2_(hA, w01, a01); a23 = fma2_(hA, w23, a23);
            b01 = fma2_(hB, w01, b01); b23 = fma2_(hB, w23, b23);
        }
        float x0, x1, x2, x3, y0, y1, y2, y3;
        upk2(x0, x1, a01); upk2(x2, x3, a23);
        upk2(y0, y1, b01); upk2(y2, y3, b23);
        x0 = va ? fmaxf(x0, 0.f) : -CUDART_INF_F;
        x1 = va ? fmaxf(x1, 0.f) : -CUDART_INF_F;
        x2 = va ? fmaxf(x2, 0.f) : -CUDART_INF_F;
        x3 = va ? fmaxf(x3, 0.f) : -CUDART_INF_F;
        y0 = vb ? fmaxf(y0, 0.f) : -CUDART_INF_F;
        y1 = vb ? fmaxf(y1, 0.f) : -CUDART_INF_F;
        y2 = vb ? fmaxf(y2, 0.f) : -CUDART_INF_F;
        y3 = vb ? fmaxf(y3, 0.f) : -CUDART_INF_F;
        float v0 = fmaxf(x0, y0), v1 = fmaxf(x1, y1);
        float v2 = fmaxf(x2, y2), v3 = fmaxf(x3, y3);
#pragma unroll
        for (int off = 16; off; off >>= 1) {
            v0 = fmaxf(v0, __shfl_down_sync(FULLMASK, v0, off));
            v1 = fmaxf(v1, __shfl_down_sync(FULLMASK, v1, off));
            v2 = fmaxf(v2, __shfl_down_sync(FULLMASK, v2, off));
            v3 = fmaxf(v3, __shfl_down_sync(FULLMASK, v3, off));
        }
        if (lane == 0)
            *reinterpret_cast<float4*>(out + (size_t)q * COUT + cg * 4) =
                make_float4(v0, v1, v2, v3);
    }
}

extern "C" void kernel_launch(void* const* d_in, const int* in_sizes, int n_in,
                              void* d_out, int out_size)
{
    const float* x   = (const float*)d_in[0];
    const float* w1a = (const float*)d_in[1];  const float* b1a = (const float*)d_in[2];
    const float* w1b = (const float*)d_in[3];  const float* b1b = (const float*)d_in[4];
    const float* w1c = (const float*)d_in[5];  const float* b1c = (const float*)d_in[6];
    const float* w2a = (const float*)d_in[7];  const float* b2a = (const float*)d_in[8];
    const float* w2b = (const float*)d_in[9];  const float* b2b = (const float*)d_in[10];
    const float* w2c = (const float*)d_in[11]; const float* b2c = (const float*)d_in[12];
    float* out = (float*)d_out;

    void *pq1, *pq2, *pn1, *pn2, *pc1, *pc2, *pf1, *pa, *pb;
    cudaGetSymbolAddress(&pq1, g_qpos1);
    cudaGetSymbolAddress(&pq2, g_qpos2);
    cudaGetSymbolAddress(&pn1, g_nidx1);
    cudaGetSymbolAddress(&pn2, g_nidx2);
    cudaGetSymbolAddress(&pc1, g_cnt1);
    cudaGetSymbolAddress(&pc2, g_cnt2);
    cudaGetSymbolAddress(&pf1, g_feat1);
    cudaGetSymbolAddress(&pa, g_bufA);
    cudaGetSymbolAddress(&pb, g_bufB);
    float* qpos1 = (float*)pq1;  float* qpos2 = (float*)pq2;
    int* nidx1 = (int*)pn1;      int* nidx2 = (int*)pn2;
    int* cnt1 = (int*)pc1;       int* cnt2 = (int*)pc2;
    float* feat1 = (float*)pf1;  float* bufA = (float*)pa;  float* bufB = (float*)pb;

    // fps1 needs 64KB dynamic smem (4096 float4)
    cudaFuncSetAttribute((const void*)fps_kernel<16, 256>,
                         cudaFuncAttributeMaxDynamicSharedMemorySize, Nc * 16);

    const int featN = Bc * S2 * 128;
    const int posN = Bc * S2 * 3;
    int mode = 0;
    if (out_size >= featN + posN) mode = 1;
    if (out_size >= featN + posN + Bc * S2) mode = 2;

    // K1: fps stage1 (N=4096 -> S1=2048)
    fps_kernel<16, 256><<<Bc, 256, Nc * 16>>>(x, 6, Nc, S1, qpos1);

    // K2: fps stage2 overlapped with ball query stage1
    {
        int ballBlks = (Bc * S1) / 8;
        k2_fps2_ball1<<<Bc + ballBlks, 256, S1 * 16>>>(x, qpos1, qpos2, nidx1, cnt1);
    }

    // K3: ball query stage2 overlapped with fully-fused stage1 MLP+maxpool
    {
        int fusedBlks = (Bc * S1) / 4;          // 2048
        k3_ball2_fused1<<<BALL2_BLKS + fusedBlks, 128>>>(
            x, qpos1, qpos2, nidx2, cnt2, nidx1, cnt1,
            w1a, b1a, w1b, b1b, w1c, b1c, feat1);
    }

    // K4/K5: stage2 MLP A, B
    layerA2_kernel<<<(Bc * S2 * Kc) / 128, 128>>>(feat1, qpos1, qpos2, nidx2, w2a, b2a, bufA);
    layerB2_kernel<<<(Bc * S2 * Kc) / 128, 128>>>(bufA, w2b, b2b, bufB);

    // K6: stage2 layer C + maxpool, with tail blocks for optional pos/batch outputs
    {
        int nq = (Bc * S2) / 4;
        int tailBlks = (posN + 127) / 128 + 1;
        layerC_kernel<64, 128, 128, true><<<nq + tailBlks, 128>>>(
            bufB, cnt2, w2c, b2c, out, Bc * S2, qpos2, mode);
    }
}